// round 4
// baseline (speedup 1.0000x reference)
#include <cuda_runtime.h>
#include <cuda_bf16.h>
#include <math.h>

// ---------------------------------------------------------------------------
// Problem dims
// ---------------------------------------------------------------------------
#define VB   64            // batch
#define TT   512           // seq len
#define UU   256           // hidden per direction
#define GGN  768           // 3*U
#define MM   (VB*TT)       // 32768 projection rows
#define CC   20            // classes

// ---------------------------------------------------------------------------
// Scratch (device globals; allocation is forbidden)
// ---------------------------------------------------------------------------
__device__ float g_xw[2][MM][GGN];    // input projections per direction (reused by layer 2)
__device__ float g_h1[VB][TT][2*UU];  // layer-1 output, concat(fwd | bwd)
__device__ float g_h2[VB][2*UU];      // layer-2 final states, concat(f_last | b_first)

// ---------------------------------------------------------------------------
// Helpers
// ---------------------------------------------------------------------------
typedef unsigned long long u64;

__device__ __forceinline__ u64 pack2(float a, float b) {
    u64 r; asm("mov.b64 %0, {%1,%2};" : "=l"(r) : "f"(a), "f"(b)); return r;
}
__device__ __forceinline__ void fma2(u64& d, u64 a, u64 b) {
    asm("fma.rn.f32x2 %0, %1, %2, %0;" : "+l"(d) : "l"(a), "l"(b));
}
__device__ __forceinline__ u64 add2(u64 a, u64 b) {
    u64 r; asm("add.rn.f32x2 %0, %1, %2;" : "=l"(r) : "l"(a), "l"(b)); return r;
}
__device__ __forceinline__ float lohi_sum(u64 v) {
    unsigned lo, hi; asm("mov.b64 {%0,%1}, %2;" : "=r"(lo), "=r"(hi) : "l"(v));
    return __uint_as_float(lo) + __uint_as_float(hi);
}
__device__ __forceinline__ void unpack2(u64 v, float& a, float& b) {
    unsigned lo, hi; asm("mov.b64 {%0,%1}, %2;" : "=r"(lo), "=r"(hi) : "l"(v));
    a = __uint_as_float(lo); b = __uint_as_float(hi);
}
__device__ __forceinline__ u64 shflx64(u64 v, int m) {
    unsigned lo = (unsigned)v, hi = (unsigned)(v >> 32);
    lo = __shfl_xor_sync(0xffffffffu, lo, m);
    hi = __shfl_xor_sync(0xffffffffu, hi, m);
    return ((u64)hi << 32) | (u64)lo;
}
__device__ __forceinline__ unsigned smem_u32(const void* p) {
    unsigned a;
    asm("{ .reg .u64 t; cvta.to.shared.u64 t, %1; cvt.u32.u64 %0, t; }" : "=r"(a) : "l"(p));
    return a;
}
__device__ __forceinline__ void st_cluster_f32(unsigned addr, int rank, float v) {
    unsigned r;
    asm("mapa.shared::cluster.u32 %0, %1, %2;" : "=r"(r) : "r"(addr), "r"(rank));
    asm volatile("st.shared::cluster.f32 [%0], %1;" :: "r"(r), "f"(v) : "memory");
}
__device__ __forceinline__ void cluster_sync_() {
    asm volatile("barrier.cluster.arrive.aligned;" ::: "memory");
    asm volatile("barrier.cluster.wait.aligned;"   ::: "memory");
}
__device__ __forceinline__ float fast_sigmoid(float x) {
    return 1.f / (1.f + __expf(-x));
}
__device__ __forceinline__ float fast_tanh(float x) {
    x = fminf(fmaxf(x, -15.f), 15.f);
    float t = __expf(-2.f * x);
    return (1.f - t) / (1.f + t);
}

// ---------------------------------------------------------------------------
// Projection GEMM: g_xw[dir][m][g] = A[m][:] @ W[:][g] + b0[g]
//   gather==1 (layer 1): A row m = emb[x[m]], K=300
//   gather==0 (layer 2): A row m = g_h1 flat [m][512], K=512
// 128x128 tiles, BK=8, 256 threads, 8x8 microtile with fma.rn.f32x2.
// Grid: (MM/128, GGN/128, 2 dirs)
// ---------------------------------------------------------------------------
__global__ __launch_bounds__(256) void proj_kernel(
    const float* __restrict__ emb, const int* __restrict__ xi,
    const float* __restrict__ Wf, const float* __restrict__ Wb,
    const float* __restrict__ bf, const float* __restrict__ bb,
    int K, int gather)
{
    const int dir = blockIdx.z;
    const float* Wm   = dir ? Wb : Wf;
    const float* bias = dir ? bb : bf;   // row 0 of [2,G]
    float* Out = &g_xw[dir][0][0];

    __shared__ float As[8][128];
    __shared__ float Bs[8][128];

    const int tid = threadIdx.x;
    const int m0 = blockIdx.x * 128;
    const int n0 = blockIdx.y * 128;
    const int tx = tid & 15, ty = tid >> 4;

    u64 acc[8][4];
#pragma unroll
    for (int i = 0; i < 8; i++)
#pragma unroll
        for (int j = 0; j < 4; j++) acc[i][j] = 0ull;

    // A loader: 2 threads per row, 4 consecutive k each
    const int lm = tid >> 1;
    const int kpart = (tid & 1) * 4;
    const float* Arow;
    if (gather) Arow = emb + (size_t)xi[m0 + lm] * K;
    else        Arow = &g_h1[0][0][0] + (size_t)(m0 + lm) * K;

    // B loader: one float4 per thread
    const int bkk = tid >> 5;
    const int bn  = (tid & 31) * 4;

    const int ktiles = (K + 7) / 8;
    for (int kt = 0; kt < ktiles; ++kt) {
        const int k0 = kt * 8;
#pragma unroll
        for (int q = 0; q < 4; ++q) {
            int k = k0 + kpart + q;
            As[kpart + q][lm] = (k < K) ? Arow[k] : 0.f;
        }
        {
            int k = k0 + bkk;
            float4 v = make_float4(0.f, 0.f, 0.f, 0.f);
            if (k < K) v = *(const float4*)(Wm + (size_t)k * GGN + n0 + bn);
            *(float4*)&Bs[bkk][bn] = v;
        }
        __syncthreads();
#pragma unroll
        for (int kk = 0; kk < 8; ++kk) {
            float a[8];
            *(float4*)&a[0] = *(const float4*)&As[kk][ty * 8];
            *(float4*)&a[4] = *(const float4*)&As[kk][ty * 8 + 4];
            float4 b0 = *(const float4*)&Bs[kk][tx * 8];
            float4 b1 = *(const float4*)&Bs[kk][tx * 8 + 4];
            u64 bp[4];
            bp[0] = pack2(b0.x, b0.y); bp[1] = pack2(b0.z, b0.w);
            bp[2] = pack2(b1.x, b1.y); bp[3] = pack2(b1.z, b1.w);
#pragma unroll
            for (int i = 0; i < 8; i++) {
                u64 as = pack2(a[i], a[i]);
#pragma unroll
                for (int j = 0; j < 4; j++) fma2(acc[i][j], as, bp[j]);
            }
        }
        __syncthreads();
    }

#pragma unroll
    for (int i = 0; i < 8; i++) {
        const int m = m0 + ty * 8 + i;
        float* orow = Out + (size_t)m * GGN + n0 + tx * 8;
#pragma unroll
        for (int j = 0; j < 2; j++) {
            float v0, v1, v2, v3;
            unpack2(acc[i][2 * j + 0], v0, v1);
            unpack2(acc[i][2 * j + 1], v2, v3);
            float4 v;
            v.x = v0 + bias[n0 + tx * 8 + j * 4 + 0];
            v.y = v1 + bias[n0 + tx * 8 + j * 4 + 1];
            v.z = v2 + bias[n0 + tx * 8 + j * 4 + 2];
            v.w = v3 + bias[n0 + tx * 8 + j * 4 + 3];
            *(float4*)(orow + j * 4) = v;
        }
    }
}

// ---------------------------------------------------------------------------
// Recurrence. Grid: 128 CTAs as 16 clusters of 8.
//   cluster c: dir = c>>3, batch-group bg = c&7 (batch elems bg*8..bg*8+7)
//   CTA rank r owns hidden units [r*32, r*32+32)
// Thread (kg = tid&7, ul = tid>>3):
//   owns unit ug = rank*32 + ul, k-slice {2*kg + 16*i | i=0..15} (pairs)
//   weights register-stationary: 48 f32x2 (3 gates x 16 k-pairs)
//   accumulates partials for all 8 batch elems, shfl-fold reduces over kg,
//   finalizes batch b = kg, broadcasts new h to all 8 CTAs' smem copies.
// One cluster.sync per step.
// ---------------------------------------------------------------------------
__global__ void __cluster_dims__(8, 1, 1) __launch_bounds__(256, 1)
rec_kernel(const float* __restrict__ rkf, const float* __restrict__ rkb,
           const float* __restrict__ biasf, const float* __restrict__ biasb,
           int layer)
{
    __shared__ float hs[2][8][UU];   // [buffer][batch-in-group][unit]

    const int cta  = blockIdx.x;
    const int rank = cta & 7;
    const int cl   = cta >> 3;
    const int dir  = cl >> 3;
    const int bg   = cl & 7;

    const float* rk   = dir ? rkb   : rkf;
    const float* bias = dir ? biasb : biasf;   // [2,G]; row 1 = recurrent bias
    const float* xw   = &g_xw[dir][0][0];

    const int tid = threadIdx.x;
    const int kg  = tid & 7;
    const int ul  = tid >> 3;
    const int ug  = rank * 32 + ul;
    const int bo  = bg * 8 + kg;      // batch elem this thread finalizes

    // ---- load recurrent weights into registers (f32x2 over k-pairs) ----
    u64 rz[16], rr[16], rh[16];
#pragma unroll
    for (int i = 0; i < 16; i++) {
        const int k = 2 * kg + 16 * i;
        rz[i] = pack2(rk[(size_t)k * GGN + ug],
                      rk[(size_t)(k + 1) * GGN + ug]);
        rr[i] = pack2(rk[(size_t)k * GGN + UU + ug],
                      rk[(size_t)(k + 1) * GGN + UU + ug]);
        rh[i] = pack2(rk[(size_t)k * GGN + 2 * UU + ug],
                      rk[(size_t)(k + 1) * GGN + 2 * UU + ug]);
    }
    const float rbz = bias[GGN + ug];
    const float rbr = bias[GGN + UU + ug];
    const float rbh = bias[GGN + 2 * UU + ug];

    for (int i = tid; i < 2 * 8 * UU; i += 256) ((float*)hs)[i] = 0.f;
    cluster_sync_();   // all buffers zeroed cluster-wide before step 0

    const unsigned hbase = smem_u32(hs);

    int p = 0;
    for (int s = 0; s < TT; ++s) {
        const int t = dir ? (TT - 1 - s) : s;

        // own-cell input projections (issued early; latency hidden by k-loop)
        const float* xwr = xw + ((size_t)bo * TT + t) * GGN;
        const float xz = xwr[ug];
        const float xr = xwr[UU + ug];
        const float xh = xwr[2 * UU + ug];

        u64 az[8], ar[8], ah[8];
#pragma unroll
        for (int b = 0; b < 8; b++) { az[b] = 0ull; ar[b] = 0ull; ah[b] = 0ull; }

        const float* hcur = &hs[p][0][0];
#pragma unroll
        for (int i = 0; i < 16; i++) {
            const int k = 2 * kg + 16 * i;
#pragma unroll
            for (int b = 0; b < 8; b++) {
                u64 hp = *(const u64*)(hcur + b * UU + k);
                fma2(az[b], rz[i], hp);
                fma2(ar[b], rr[i], hp);
                fma2(ah[b], rh[i], hp);
            }
        }

        // fold-reduce over the 8 kg threads; thread ends with full sums for b = kg
#pragma unroll
        for (int half = 4; half >= 1; half >>= 1) {
            const bool up = (kg & half) != 0;
#pragma unroll
            for (int j = 0; j < 4; j++) {
                if (j >= half) break;
                const int keep = up ? half + j : j;
                const int send = up ? j : half + j;
                az[j] = add2(az[keep], shflx64(az[send], half));
                ar[j] = add2(ar[keep], shflx64(ar[send], half));
                ah[j] = add2(ah[keep], shflx64(ah[send], half));
            }
        }

        const float rzs = lohi_sum(az[0]) + rbz;
        const float rrs = lohi_sum(ar[0]) + rbr;
        const float rhs_ = lohi_sum(ah[0]) + rbh;

        const float z  = fast_sigmoid(xz + rzs);
        const float r  = fast_sigmoid(xr + rrs);
        const float hh = fast_tanh(xh + r * rhs_);
        const float hprev = hs[p][kg][ug];
        const float hn = z * hprev + (1.f - z) * hh;

        // broadcast new h to all 8 CTAs' buffers
        const unsigned dst = hbase + (unsigned)(((p ^ 1) * 8 * UU + kg * UU + ug) * 4);
#pragma unroll
        for (int rd = 0; rd < 8; rd++) st_cluster_f32(dst, rd, hn);

        if (layer == 1) {
            g_h1[bo][t][dir * UU + ug] = hn;
        } else if (s == TT - 1) {
            g_h2[bo][dir * UU + ug] = hn;
        }

        cluster_sync_();
        p ^= 1;
    }
}

// ---------------------------------------------------------------------------
// Output: softmax(g_h2 @ wout + bout). 64 blocks x 32 threads.
// ---------------------------------------------------------------------------
__global__ __launch_bounds__(32) void out_kernel(
    const float* __restrict__ wout, const float* __restrict__ bout,
    float* __restrict__ out)
{
    __shared__ float h[2 * UU];
    __shared__ float sv[32];
    const int b = blockIdx.x, tid = threadIdx.x;

    for (int i = tid; i < 2 * UU; i += 32) h[i] = g_h2[b][i];
    __syncthreads();

    float s = 0.f;
    if (tid < CC) {
        for (int k = 0; k < 2 * UU; k++) s += h[k] * wout[(size_t)k * CC + tid];
        s += bout[tid];
    }
    sv[tid] = (tid < CC) ? s : -1e30f;
    __syncthreads();

    if (tid < CC) {
        float mx = -1e30f;
        for (int j = 0; j < CC; j++) mx = fmaxf(mx, sv[j]);
        float sum = 0.f;
        for (int j = 0; j < CC; j++) sum += expf(sv[j] - mx);
        out[b * CC + tid] = expf(s - mx) / sum;
    }
}

// ---------------------------------------------------------------------------
// Launch
// ---------------------------------------------------------------------------
extern "C" void kernel_launch(void* const* d_in, const int* in_sizes, int n_in,
                              void* d_out, int out_size) {
    (void)in_sizes; (void)n_in; (void)out_size;
    const int*   x    = (const int*)  d_in[0];
    const float* emb  = (const float*)d_in[1];
    const float* k1f  = (const float*)d_in[2];
    const float* rk1f = (const float*)d_in[3];
    const float* b1f  = (const float*)d_in[4];
    const float* k1b  = (const float*)d_in[5];
    const float* rk1b = (const float*)d_in[6];
    const float* b1b  = (const float*)d_in[7];
    const float* k2f  = (const float*)d_in[8];
    const float* rk2f = (const float*)d_in[9];
    const float* b2f  = (const float*)d_in[10];
    const float* k2b  = (const float*)d_in[11];
    const float* rk2b = (const float*)d_in[12];
    const float* b2b  = (const float*)d_in[13];
    const float* wout = (const float*)d_in[14];
    const float* bout = (const float*)d_in[15];
    float* out = (float*)d_out;

    dim3 pgrid(MM / 128, GGN / 128, 2);

    // Layer 1: input projections from embeddings, then bidirectional scan
    proj_kernel<<<pgrid, 256>>>(emb, x, k1f, k1b, b1f, b1b, 300, 1);
    rec_kernel<<<128, 256>>>(rk1f, rk1b, b1f, b1b, 1);

    // Layer 2: projections from h1, then bidirectional scan (final states only)
    proj_kernel<<<pgrid, 256>>>(emb, x, k2f, k2b, b2f, b2b, 2 * UU, 0);
    rec_kernel<<<128, 256>>>(rk2f, rk2b, b2f, b2b, 2);

    out_kernel<<<VB, 32>>>(wout, bout, out);
}